// round 2
// baseline (speedup 1.0000x reference)
#include <cuda_runtime.h>
#include <cuda_bf16.h>

#define NDIM    7500
#define NF4     1875         // NDIM/4
#define NATOMS  2500
#define NGRP    625          // NATOMS/4
#define PI_F    3.14159265358979f
#define TWO_PI  6.28318530717959f

// Packed per-z-row params: [2i] = {isb, -mb*isb, isa, -ma*isa}, [2i+1] = {md, isd, 0, 0}
__device__ float4 g_pack[2 * 2560];

__device__ __forceinline__ float rsqrt_ap(float x) {
    float r; asm("rsqrt.approx.f32 %0, %1;" : "=f"(r) : "f"(x)); return r;
}
__device__ __forceinline__ float sqrt_ap(float x) {
    float r; asm("sqrt.approx.f32 %0, %1;" : "=f"(r) : "f"(x)); return r;
}
__device__ __forceinline__ float rcp_ap(float x) {
    float r; asm("rcp.approx.f32 %0, %1;" : "=f"(r) : "f"(x)); return r;
}

// Hastings-style acos, |err| ~1e-7 rad, x in [-1,1].
__device__ __forceinline__ float acos_fast(float x) {
    float xa = fabsf(x);
    float p = -0.0012624911f;
    p = fmaf(p, xa,  0.0066700901f);
    p = fmaf(p, xa, -0.0170881256f);
    p = fmaf(p, xa,  0.0308918810f);
    p = fmaf(p, xa, -0.0501743046f);
    p = fmaf(p, xa,  0.0889789874f);
    p = fmaf(p, xa, -0.2145988016f);
    p = fmaf(p, xa,  1.5707963050f);
    float r = sqrt_ap(1.0f - xa) * p;
    return (x >= 0.0f) ? r : (PI_F - r);
}

// Full-quadrant atan2, |err| ~ few e-6 rad.
__device__ __forceinline__ float atan2_fast(float y, float x) {
    float ax = fabsf(x), ay = fabsf(y);
    float mx = fmaxf(fmaxf(ax, ay), 1e-35f);
    float mn = fminf(ax, ay);
    float t  = mn * rcp_ap(mx);
    float s  = t * t;
    float p = -0.01172120f;
    p = fmaf(p, s,  0.05265332f);
    p = fmaf(p, s, -0.11643287f);
    p = fmaf(p, s,  0.19354346f);
    p = fmaf(p, s, -0.33262347f);
    p = fmaf(p, s,  0.99997726f);
    float r = t * p;
    if (ay > ax)   r = 1.57079632679f - r;
    if (x < 0.0f)  r = PI_F - r;
    return copysignf(r, y);
}

__global__ void prep_kernel(const float* __restrict__ mb, const float* __restrict__ sb,
                            const float* __restrict__ ma, const float* __restrict__ sa,
                            const float* __restrict__ md, const float* __restrict__ sd,
                            int zrows)
{
    int i = blockIdx.x * blockDim.x + threadIdx.x;
    if (i < zrows) {
        float isb = rcp_ap(sb[i]);
        float isa = rcp_ap(sa[i]);
        float isd = rcp_ap(sd[i]);
        g_pack[2 * i]     = make_float4(isb, -mb[i] * isb, isa, -ma[i] * isa);
        g_pack[2 * i + 1] = make_float4(md[i], isd, 0.0f, 0.0f);
    }
}

__global__ __launch_bounds__(256)
void ict_kernel(const float* __restrict__ x,
                const int4*  __restrict__ zmat,
                float* __restrict__ out, int zrows)
{
    __shared__ float4 srow[NATOMS];     // atom j -> {x,y,z,pad}, 40KB
    const int b   = blockIdx.x;
    const int tid = threadIdx.x;
    const size_t base = (size_t)b * NDIM;

    // Stage: 4 atoms (= 3 float4 of gmem) per group, repack into padded smem.
    const float4* __restrict__ xin = (const float4*)(x + base);
#pragma unroll
    for (int k = 0; k < 3; k++) {
        int g = tid + k * 256;
        if (g < NGRP) {
            float4 f0 = xin[3 * g];
            float4 f1 = xin[3 * g + 1];
            float4 f2 = xin[3 * g + 2];
            srow[4 * g]     = make_float4(f0.x, f0.y, f0.z, 0.0f);
            srow[4 * g + 1] = make_float4(f0.w, f1.x, f1.y, 0.0f);
            srow[4 * g + 2] = make_float4(f1.z, f1.w, f2.x, 0.0f);
            srow[4 * g + 3] = make_float4(f2.y, f2.z, f2.w, 0.0f);
        }
    }
    __syncthreads();

    // First 9 output floats (atoms 0..2) are a straight copy.
    if (tid < 9) out[base + tid] = x[base + tid];

    for (int i = tid; i < zrows; i += 256) {
        int4 zm = zmat[i];            // (a4, a1, a2, a3)
        float4 P1 = srow[zm.y];
        float4 P2 = srow[zm.z];
        float4 P3 = srow[zm.w];
        float4 P4 = srow[zm.x];
        float4 pk0 = g_pack[2 * i];
        float4 pk1 = g_pack[2 * i + 1];

        float d21x = P2.x - P1.x, d21y = P2.y - P1.y, d21z = P2.z - P1.z;
        float d41x = P4.x - P1.x, d41y = P4.y - P1.y, d41z = P4.z - P1.z;

        float s21 = fmaf(d21x, d21x, fmaf(d21y, d21y, d21z * d21z));
        float s41 = fmaf(d41x, d41x, fmaf(d41y, d41y, d41z * d41z));
        float r21 = rsqrt_ap(s21);
        float r41 = rsqrt_ap(s41);

        float bond = s41 * r41;       // |p4 - p1|

        // angle between unit(p2-p1) and unit(p4-p1)
        float dotc = fmaf(d21x, d41x, fmaf(d21y, d41y, d21z * d41z));
        float cosang = fminf(fmaxf(dotc * r21 * r41, -1.0f), 1.0f);
        float ang = acos_fast(cosang);

        // dihedral: u = unit(p2-p1) = -b1; sign flip absorbed into atan2 args.
        float ux = d21x * r21, uy = d21y * r21, uz = d21z * r21;
        float b0x = P3.x - P2.x, b0y = P3.y - P2.y, b0z = P3.z - P2.z;

        float db0 = fmaf(b0x, ux, fmaf(b0y, uy, b0z * uz));
        float vx = fmaf(-db0, ux, b0x);
        float vy = fmaf(-db0, uy, b0y);
        float vz = fmaf(-db0, uz, b0z);

        float db2 = fmaf(d41x, ux, fmaf(d41y, uy, d41z * uz));
        float wx = fmaf(-db2, ux, d41x);
        float wy = fmaf(-db2, uy, d41y);
        float wz = fmaf(-db2, uz, d41z);

        float xx = fmaf(vx, wx, fmaf(vy, wy, vz * wz));
        float cx = fmaf(uy, vz, -uz * vy);
        float cy = fmaf(uz, vx, -ux * vz);
        float cz = fmaf(ux, vy, -uy * vx);
        float yy = fmaf(cx, wx, fmaf(cy, wy, cz * wz));
        float dihe = atan2_fast(yy, xx);

        // normalize with pre-packed params
        float ob = fmaf(bond, pk0.x, pk0.y);
        float oa = fmaf(ang,  pk0.z, pk0.w);
        float dd = dihe - pk1.x;
        dd = (dd < -PI_F) ? dd + TWO_PI : dd;
        dd = (dd >  PI_F) ? dd - TWO_PI : dd;
        float od = dd * pk1.y;

        float* o = out + base + 3 * zm.x;
        o[0] = ob;
        o[1] = oa;
        o[2] = od;
    }
}

extern "C" void kernel_launch(void* const* d_in, const int* in_sizes, int n_in,
                              void* d_out, int out_size)
{
    const float* x  = (const float*)d_in[0];
    const int*   zm = (const int*)  d_in[1];
    const float* mb = (const float*)d_in[2];
    const float* sb = (const float*)d_in[3];
    const float* ma = (const float*)d_in[4];
    const float* sa = (const float*)d_in[5];
    const float* md = (const float*)d_in[6];
    const float* sd = (const float*)d_in[7];

    int bsz   = in_sizes[0] / NDIM;   // 2048
    int zrows = in_sizes[2];          // 2497

    prep_kernel<<<(zrows + 255) / 256, 256>>>(mb, sb, ma, sa, md, sd, zrows);
    ict_kernel<<<bsz, 256>>>(x, (const int4*)zm, (float*)d_out, zrows);
}

// round 3
// speedup vs baseline: 1.4923x; 1.4923x over previous
#include <cuda_runtime.h>
#include <cuda_bf16.h>

// InternalCoordinateTransform. Exploits the z-matrix structure:
// z_mat row r = (r+3, r+2, r+1, r)  (atoms of a row are consecutive),
// which the reference builds as stack([atoms, atoms-1, atoms-2, atoms-3]).
// => row r needs atoms r..r+3 = floats 3r..3r+11 (contiguous), and writes
//    floats 3r+9..3r+11. Grouping rows 4g+1..4g+4 per thread makes both the
//    loads (floats 12g..12g+23) and stores (floats 12g+12..12g+23) 16B-aligned.

#define NDIM    7500
#define NF4     1875          // NDIM/4
#define ZROWS   2497
#define NGROUPS 624           // rows 1..2496 in groups of 4; row 0 special
#define PI_F    3.14159265358979f
#define TWO_PI  6.28318530717959f

// Group-SoA packed params: g_prm[k*NGROUPS + g], k=0..5:
// {isb}, {-mb*isb}, {isa}, {-ma*isa}, {md}, {isd} for rows 4g+1..4g+4.
__device__ float4 g_prm[6 * NGROUPS];

__device__ __forceinline__ float rsqrt_ap(float x) {
    float r; asm("rsqrt.approx.f32 %0, %1;" : "=f"(r) : "f"(x)); return r;
}
__device__ __forceinline__ float sqrt_ap(float x) {
    float r; asm("sqrt.approx.f32 %0, %1;" : "=f"(r) : "f"(x)); return r;
}
__device__ __forceinline__ float rcp_ap(float x) {
    float r; asm("rcp.approx.f32 %0, %1;" : "=f"(r) : "f"(x)); return r;
}

// Hastings-style acos, |err| ~1e-7 rad, x in [-1,1].
__device__ __forceinline__ float acos_fast(float x) {
    float xa = fabsf(x);
    float p = -0.0012624911f;
    p = fmaf(p, xa,  0.0066700901f);
    p = fmaf(p, xa, -0.0170881256f);
    p = fmaf(p, xa,  0.0308918810f);
    p = fmaf(p, xa, -0.0501743046f);
    p = fmaf(p, xa,  0.0889789874f);
    p = fmaf(p, xa, -0.2145988016f);
    p = fmaf(p, xa,  1.5707963050f);
    float r = sqrt_ap(1.0f - xa) * p;
    return (x >= 0.0f) ? r : (PI_F - r);
}

// Full-quadrant atan2, |err| ~ few e-6 rad.
__device__ __forceinline__ float atan2_fast(float y, float x) {
    float ax = fabsf(x), ay = fabsf(y);
    float mx = fmaxf(fmaxf(ax, ay), 1e-35f);
    float mn = fminf(ax, ay);
    float t  = mn * rcp_ap(mx);
    float s  = t * t;
    float p = -0.01172120f;
    p = fmaf(p, s,  0.05265332f);
    p = fmaf(p, s, -0.11643287f);
    p = fmaf(p, s,  0.19354346f);
    p = fmaf(p, s, -0.33262347f);
    p = fmaf(p, s,  0.99997726f);
    float r = t * p;
    if (ay > ax)   r = 1.57079632679f - r;
    if (x < 0.0f)  r = PI_F - r;
    return copysignf(r, y);
}

// Compute (bond, angle, dihedral) for one z-row given atoms r..r+3.
// p3 = atom r, p2 = atom r+1, p1 = atom r+2, p4 = atom r+3.
__device__ __forceinline__ void ic_row(
    const float* a,  // 12 floats: atom r..r+3 coords
    float& bond, float& ang, float& dihe)
{
    float p3x = a[0],  p3y = a[1],  p3z = a[2];
    float p2x = a[3],  p2y = a[4],  p2z = a[5];
    float p1x = a[6],  p1y = a[7],  p1z = a[8];
    float p4x = a[9],  p4y = a[10], p4z = a[11];

    float d21x = p2x - p1x, d21y = p2y - p1y, d21z = p2z - p1z;
    float d41x = p4x - p1x, d41y = p4y - p1y, d41z = p4z - p1z;

    float s21 = fmaf(d21x, d21x, fmaf(d21y, d21y, d21z * d21z));
    float s41 = fmaf(d41x, d41x, fmaf(d41y, d41y, d41z * d41z));
    float r21 = rsqrt_ap(s21);
    float r41 = rsqrt_ap(s41);

    bond = s41 * r41;

    float dotc = fmaf(d21x, d41x, fmaf(d21y, d41y, d21z * d41z));
    float cosang = fminf(fmaxf(dotc * r21 * r41, -1.0f), 1.0f);
    ang = acos_fast(cosang);

    // u = unit(p2-p1) = -b1; sign flip absorbed into atan2.
    float ux = d21x * r21, uy = d21y * r21, uz = d21z * r21;
    float b0x = p3x - p2x, b0y = p3y - p2y, b0z = p3z - p2z;

    float db0 = fmaf(b0x, ux, fmaf(b0y, uy, b0z * uz));
    float vx = fmaf(-db0, ux, b0x);
    float vy = fmaf(-db0, uy, b0y);
    float vz = fmaf(-db0, uz, b0z);

    float db2 = fmaf(d41x, ux, fmaf(d41y, uy, d41z * uz));
    float wx = fmaf(-db2, ux, d41x);
    float wy = fmaf(-db2, uy, d41y);
    float wz = fmaf(-db2, uz, d41z);

    float xx = fmaf(vx, wx, fmaf(vy, wy, vz * wz));
    float cx = fmaf(uy, vz, -uz * vy);
    float cy = fmaf(uz, vx, -ux * vz);
    float cz = fmaf(ux, vy, -uy * vx);
    float yy = fmaf(cx, wx, fmaf(cy, wy, cz * wz));
    dihe = atan2_fast(yy, xx);
}

__global__ void prep_kernel(const float* __restrict__ mb, const float* __restrict__ sb,
                            const float* __restrict__ ma, const float* __restrict__ sa,
                            const float* __restrict__ md, const float* __restrict__ sd)
{
    int g = blockIdx.x * blockDim.x + threadIdx.x;
    if (g >= NGROUPS) return;
    float4 v0, v1, v2, v3, v4, v5;
    float* p0 = (float*)&v0; float* p1 = (float*)&v1; float* p2 = (float*)&v2;
    float* p3 = (float*)&v3; float* p4 = (float*)&v4; float* p5 = (float*)&v5;
#pragma unroll
    for (int j = 0; j < 4; j++) {
        int r = 4 * g + 1 + j;
        float isb = rcp_ap(sb[r]);
        float isa = rcp_ap(sa[r]);
        float isd = rcp_ap(sd[r]);
        p0[j] = isb;  p1[j] = -mb[r] * isb;
        p2[j] = isa;  p3[j] = -ma[r] * isa;
        p4[j] = md[r]; p5[j] = isd;
    }
    g_prm[0 * NGROUPS + g] = v0;
    g_prm[1 * NGROUPS + g] = v1;
    g_prm[2 * NGROUPS + g] = v2;
    g_prm[3 * NGROUPS + g] = v3;
    g_prm[4 * NGROUPS + g] = v4;
    g_prm[5 * NGROUPS + g] = v5;
}

__global__ __launch_bounds__(256)
void ict_kernel(const float* __restrict__ x,
                const float* __restrict__ mb, const float* __restrict__ sb,
                const float* __restrict__ ma, const float* __restrict__ sa,
                const float* __restrict__ md, const float* __restrict__ sd,
                float* __restrict__ out)
{
    __shared__ float4 A4[NF4];                 // the batch row, 30KB
    const int b   = blockIdx.x;
    const int tid = threadIdx.x;
    const size_t base = (size_t)b * NDIM;
    const float*  A     = (const float*)A4;
    float4* __restrict__ outv = (float4*)(out + base);

    // Stage row (coalesced float4).
    const float4* __restrict__ xin = (const float4*)(x + base);
#pragma unroll
    for (int k = 0; k < 8; k++) {
        int idx = tid + k * 256;
        if (idx < NF4) A4[idx] = xin[idx];
    }
    __syncthreads();

    for (int g = tid; g < NGROUPS; g += 256) {
        // atoms 4g..4g+7 -> floats 12g..12g+23 (6 aligned conflict-free LDS.128)
        float a[24];
        float4 f;
#pragma unroll
        for (int q = 0; q < 6; q++) {
            f = A4[3 * g + q];
            a[4 * q]     = f.x; a[4 * q + 1] = f.y;
            a[4 * q + 2] = f.z; a[4 * q + 3] = f.w;
        }
        float4 c0 = g_prm[0 * NGROUPS + g];
        float4 c1 = g_prm[1 * NGROUPS + g];
        float4 c2 = g_prm[2 * NGROUPS + g];
        float4 c3 = g_prm[3 * NGROUPS + g];
        float4 c4 = g_prm[4 * NGROUPS + g];
        float4 c5 = g_prm[5 * NGROUPS + g];
        const float* pc0 = (const float*)&c0; const float* pc1 = (const float*)&c1;
        const float* pc2 = (const float*)&c2; const float* pc3 = (const float*)&c3;
        const float* pc4 = (const float*)&c4; const float* pc5 = (const float*)&c5;

        float res[12];
#pragma unroll
        for (int j = 0; j < 4; j++) {
            // row r = 4g+1+j: atoms r..r+3 start at local float 3*(1+j)
            float bond, ang, dihe;
            ic_row(a + 3 * (1 + j), bond, ang, dihe);
            res[3 * j]     = fmaf(bond, pc0[j], pc1[j]);
            res[3 * j + 1] = fmaf(ang,  pc2[j], pc3[j]);
            float dd = dihe - pc4[j];
            dd = (dd < -PI_F) ? dd + TWO_PI : dd;
            dd = (dd >  PI_F) ? dd - TWO_PI : dd;
            res[3 * j + 2] = dd * pc5[j];
        }
        // results = floats 12g+12..12g+23 -> f4 indices 3g+3..3g+5 (aligned)
        outv[3 * g + 3] = make_float4(res[0], res[1], res[2],  res[3]);
        outv[3 * g + 4] = make_float4(res[4], res[5], res[6],  res[7]);
        outv[3 * g + 5] = make_float4(res[8], res[9], res[10], res[11]);
    }

    // Row 0 + head (floats 0..11): one thread, 3 aligned STG.128.
    if (tid == 255) {
        float bond, ang, dihe;
        ic_row(A, bond, ang, dihe);
        float isb = rcp_ap(sb[0]);
        float isa = rcp_ap(sa[0]);
        float ob = (bond - mb[0]) * isb;
        float oa = (ang  - ma[0]) * isa;
        float dd = dihe - md[0];
        dd = (dd < -PI_F) ? dd + TWO_PI : dd;
        dd = (dd >  PI_F) ? dd - TWO_PI : dd;
        float od = dd * rcp_ap(sd[0]);
        outv[0] = make_float4(A[0], A[1], A[2], A[3]);
        outv[1] = make_float4(A[4], A[5], A[6], A[7]);
        outv[2] = make_float4(A[8], ob, oa, od);
    }
}

extern "C" void kernel_launch(void* const* d_in, const int* in_sizes, int n_in,
                              void* d_out, int out_size)
{
    const float* x  = (const float*)d_in[0];
    const float* mb = (const float*)d_in[2];
    const float* sb = (const float*)d_in[3];
    const float* ma = (const float*)d_in[4];
    const float* sa = (const float*)d_in[5];
    const float* md = (const float*)d_in[6];
    const float* sd = (const float*)d_in[7];

    int bsz = in_sizes[0] / NDIM;   // 2048

    prep_kernel<<<(NGROUPS + 255) / 256, 256>>>(mb, sb, ma, sa, md, sd);
    ict_kernel<<<bsz, 256>>>(x, mb, sb, ma, sa, md, sd, (float*)d_out);
}